// round 7
// baseline (speedup 1.0000x reference)
#include <cuda_runtime.h>
#include <cuda_bf16.h>
#include <math.h>
#include <stdint.h>

#define BATCH 64
#define TSEQ  2048
#define UNITS 512
#define EMB   256
#define ROWS  (BATCH * TSEQ)   // 131072

// ------------------------- device scratch ----------------------------------
__device__ float g_x[BATCH * UNITS];
__device__ float g_xg[BATCH * 3 * UNITS];
__device__ float g_qplus[BATCH * UNITS];
__device__ float g_reczr[BATCH * 2 * UNITS];
__device__ float g_scorepart[ROWS * 2];
__device__ float g_attn[BATCH * TSEQ];
__device__ float g_partial[BATCH * 16 * UNITS];
__device__ float g_ctxvec[BATCH * UNITS];
__device__ float g_cg[BATCH * 3 * UNITS];
__device__ float g_z[BATCH * UNITS];
__device__ float g_rh[BATCH * UNITS];
__device__ float g_h[BATCH * UNITS];
__device__ float g_gp[4 * BATCH * 3 * UNITS];        // split-K partials
__device__ __nv_bfloat16 g_WaT[UNITS * UNITS];       // [n][k], k contiguous

// ------------------------- helpers -----------------------------------------
__device__ __forceinline__ void cp16(void* dst_smem, const void* src) {
    uint32_t d = (uint32_t)__cvta_generic_to_shared(dst_smem);
    asm volatile("cp.async.cg.shared.global [%0], [%1], 16;\n" :: "r"(d), "l"(src));
}
#define CP_COMMIT() asm volatile("cp.async.commit_group;\n" ::)
#define CP_WAIT1()  asm volatile("cp.async.wait_group 1;\n" ::)
#define CP_WAIT0()  asm volatile("cp.async.wait_group 0;\n" ::)

__device__ __forceinline__ float tanh_approx(float x) {
    float y;
    asm("tanh.approx.f32 %0, %1;" : "=f"(y) : "f"(x));
    return y;
}
__device__ __forceinline__ uint32_t packbf(float a, float b) {
    __nv_bfloat162 p = __floats2bfloat162_rn(a, b);
    return *(uint32_t*)&p;
}

// ------------------------- prep: Wa -> WaT bf16 (tiled transpose) -----------
__global__ void prep_wat_kernel(const float* __restrict__ Wa,
                                __nv_bfloat16* __restrict__ WaT) {
    __shared__ float t[32][33];
    int n0 = blockIdx.x * 32, k0 = blockIdx.y * 32;
    int tx = threadIdx.x, ty = threadIdx.y;     // 32 x 8
#pragma unroll
    for (int i = 0; i < 4; i++)
        t[ty + 8 * i][tx] = Wa[(k0 + ty + 8 * i) * UNITS + n0 + tx];
    __syncthreads();
#pragma unroll
    for (int i = 0; i < 4; i++)
        WaT[(size_t)(n0 + ty + 8 * i) * UNITS + k0 + tx] =
            __float2bfloat16(t[tx][ty + 8 * i]);
}

// ------------------------- tiled small GEMM (M=64) --------------------------
// P[(blockIdx.y*64+m)*N + bx*64+n] = sum_{k in chunk} A[m][k0+k] * B[(k0+k)*ldb + bcol0 + n]
__global__ __launch_bounds__(256)
void gemm64_kernel(const float* __restrict__ A, int lda,
                   const float* __restrict__ B, int ldb, int bcol0,
                   int Kc, float* __restrict__ P, int N) {
    __shared__ float As_t[16][68];   // [k][m]
    __shared__ float Bs[16][68];     // [k][n]
    int tid = threadIdx.x;
    int tx = tid & 15, ty = tid >> 4;
    int n0 = blockIdx.x * 64;
    int k0 = blockIdx.y * Kc;

    float acc[4][4];
#pragma unroll
    for (int i = 0; i < 4; i++)
#pragma unroll
        for (int j = 0; j < 4; j++) acc[i][j] = 0.f;

    int am = tid >> 2, aj = tid & 3;          // A staging: row, float4 idx
    int bk = tid >> 4, bf = tid & 15;         // B staging: k row, float4 idx

    for (int kb = 0; kb < Kc; kb += 16) {
        float4 av = *(const float4*)&A[am * lda + k0 + kb + aj * 4];
        float4 bv = *(const float4*)&B[(size_t)(k0 + kb + bk) * ldb + bcol0 + n0 + bf * 4];
        As_t[aj * 4 + 0][am] = av.x;
        As_t[aj * 4 + 1][am] = av.y;
        As_t[aj * 4 + 2][am] = av.z;
        As_t[aj * 4 + 3][am] = av.w;
        *(float4*)&Bs[bk][bf * 4] = bv;
        __syncthreads();
#pragma unroll
        for (int k = 0; k < 16; k++) {
            float4 a = *(const float4*)&As_t[k][ty * 4];
            float4 b = *(const float4*)&Bs[k][tx * 4];
            acc[0][0] = fmaf(a.x, b.x, acc[0][0]);
            acc[0][1] = fmaf(a.x, b.y, acc[0][1]);
            acc[0][2] = fmaf(a.x, b.z, acc[0][2]);
            acc[0][3] = fmaf(a.x, b.w, acc[0][3]);
            acc[1][0] = fmaf(a.y, b.x, acc[1][0]);
            acc[1][1] = fmaf(a.y, b.y, acc[1][1]);
            acc[1][2] = fmaf(a.y, b.z, acc[1][2]);
            acc[1][3] = fmaf(a.y, b.w, acc[1][3]);
            acc[2][0] = fmaf(a.z, b.x, acc[2][0]);
            acc[2][1] = fmaf(a.z, b.y, acc[2][1]);
            acc[2][2] = fmaf(a.z, b.z, acc[2][2]);
            acc[2][3] = fmaf(a.z, b.w, acc[2][3]);
            acc[3][0] = fmaf(a.w, b.x, acc[3][0]);
            acc[3][1] = fmaf(a.w, b.y, acc[3][1]);
            acc[3][2] = fmaf(a.w, b.z, acc[3][2]);
            acc[3][3] = fmaf(a.w, b.w, acc[3][3]);
        }
        __syncthreads();
    }
#pragma unroll
    for (int i = 0; i < 4; i++) {
        float4 r = make_float4(acc[i][0], acc[i][1], acc[i][2], acc[i][3]);
        *(float4*)&P[(size_t)(blockIdx.y * 64 + ty * 4 + i) * N + n0 + tx * 4] = r;
    }
}

// reduce over split-K + biases. grid (N/256, 64)
__global__ void reduce64_kernel(const float* __restrict__ P, int N, int KS,
                                const float* __restrict__ b1,
                                const float* __restrict__ b2,
                                float* __restrict__ C, int ldc, int ccol0) {
    int m = blockIdx.y;
    int n = blockIdx.x * 256 + threadIdx.x;
    float s = 0.f;
    for (int ks = 0; ks < KS; ks++) s += P[(size_t)(ks * 64 + m) * N + n];
    if (b1) s += b1[n];
    if (b2) s += b2[n];
    C[m * ldc + ccol0 + n] = s;
}

// ------------------------- big fused score GEMM (cp.async 2-stage) ----------
#define SBM 128
#define SBN 256
#define SASTR 72   // fp32 per A smem row (64 + 8 pad)
#define SBSTR 36   // u32 per B smem row (32 + 4 pad)

__device__ __forceinline__ void score_issue(
    int tid, const float* gA, const __nv_bfloat16* gB,
    float* As, uint32_t* Bs) {
#pragma unroll
    for (int i = 0; i < 8; i++) {
        int c = tid + i * 256;
        int r = c >> 4, f = c & 15;
        cp16(As + r * SASTR + f * 4, gA + (size_t)r * UNITS + f * 4);
    }
#pragma unroll
    for (int i = 0; i < 8; i++) {
        int c = tid + i * 256;
        int n = c >> 3, j = c & 7;
        cp16(Bs + n * SBSTR + j * 4, gB + (size_t)n * UNITS + j * 8);
    }
}

__global__ __launch_bounds__(256, 1)
void score_kernel(const float* __restrict__ context,
                  const __nv_bfloat16* __restrict__ WaT,
                  const float* __restrict__ qplus,
                  const float* __restrict__ Va,
                  float* __restrict__ scorepart) {
    extern __shared__ uint32_t smem[];
    float* Ast[2];
    uint32_t* Bst[2];
    Ast[0] = (float*)smem;
    Ast[1] = Ast[0] + SBM * SASTR;
    Bst[0] = (uint32_t*)(Ast[1] + SBM * SASTR);
    Bst[1] = Bst[0] + SBN * SBSTR;

    const int tid = threadIdx.x;
    const int wid = tid >> 5;
    const int lane = tid & 31;
    const int wm = wid >> 1;
    const int wn = wid & 1;
    const size_t row0 = (size_t)blockIdx.x * SBM;
    const int b = (int)(row0 >> 11);
    const int nh = blockIdx.y;
    const int ncol0 = nh * SBN;

    const float* gA = context + row0 * UNITS;
    const __nv_bfloat16* gB = WaT + (size_t)ncol0 * UNITS;

    float acc[2][16][4];
#pragma unroll
    for (int i = 0; i < 2; i++)
#pragma unroll
        for (int j = 0; j < 16; j++)
#pragma unroll
            for (int q = 0; q < 4; q++) acc[i][j][q] = 0.f;

    score_issue(tid, gA, gB, Ast[0], Bst[0]);
    CP_COMMIT();

    for (int kt = 0; kt < 8; ++kt) {
        if (kt < 7) {
            score_issue(tid, gA + (kt + 1) * 64, gB + (kt + 1) * 64,
                        Ast[(kt + 1) & 1], Bst[(kt + 1) & 1]);
            CP_COMMIT();
            CP_WAIT1();
        } else {
            CP_WAIT0();
        }
        __syncthreads();

        const float* As = Ast[kt & 1];
        const uint32_t* Bs = Bst[kt & 1];
#pragma unroll
        for (int ks = 0; ks < 4; ks++) {
            uint32_t a[2][4];
            int kk = ks * 16 + (lane & 3) * 2;
#pragma unroll
            for (int mt = 0; mt < 2; mt++) {
                int r0 = wm * 32 + mt * 16 + (lane >> 2);
                float2 f0 = *(const float2*)&As[r0 * SASTR + kk];
                float2 f1 = *(const float2*)&As[(r0 + 8) * SASTR + kk];
                float2 f2 = *(const float2*)&As[r0 * SASTR + kk + 8];
                float2 f3 = *(const float2*)&As[(r0 + 8) * SASTR + kk + 8];
                a[mt][0] = packbf(f0.x, f0.y);
                a[mt][1] = packbf(f1.x, f1.y);
                a[mt][2] = packbf(f2.x, f2.y);
                a[mt][3] = packbf(f3.x, f3.y);
            }
#pragma unroll
            for (int nt = 0; nt < 16; nt++) {
                int n = wn * 128 + nt * 8 + (lane >> 2);
                uint32_t b0 = Bs[n * SBSTR + ks * 8 + (lane & 3)];
                uint32_t b1 = Bs[n * SBSTR + ks * 8 + 4 + (lane & 3)];
#pragma unroll
                for (int mt = 0; mt < 2; mt++) {
                    asm volatile(
                        "mma.sync.aligned.m16n8k16.row.col.f32.bf16.bf16.f32 "
                        "{%0,%1,%2,%3}, {%4,%5,%6,%7}, {%8,%9}, {%0,%1,%2,%3};\n"
                        : "+f"(acc[mt][nt][0]), "+f"(acc[mt][nt][1]),
                          "+f"(acc[mt][nt][2]), "+f"(acc[mt][nt][3])
                        : "r"(a[mt][0]), "r"(a[mt][1]), "r"(a[mt][2]), "r"(a[mt][3]),
                          "r"(b0), "r"(b1));
                }
            }
        }
        __syncthreads();
    }

    // ---- epilogue: +qplus -> tanh -> *Va -> row reduce ----
    float* redf = (float*)smem;          // [128][2]
    float* sq = redf + 256;              // [512]
    float* sv = sq + 512;                // [512]
    for (int i = tid; i < 512; i += 256) {
        sq[i] = qplus[b * UNITS + i];
        sv[i] = Va[i];
    }
    __syncthreads();

    float rsum[2][2] = {{0.f, 0.f}, {0.f, 0.f}};
#pragma unroll
    for (int mt = 0; mt < 2; mt++) {
#pragma unroll
        for (int nt = 0; nt < 16; nt++) {
            int n0 = ncol0 + wn * 128 + nt * 8 + (lane & 3) * 2;
            float q0 = sq[n0], q1 = sq[n0 + 1];
            float v0 = sv[n0], v1 = sv[n0 + 1];
            rsum[mt][0] += tanh_approx(acc[mt][nt][0] + q0) * v0
                         + tanh_approx(acc[mt][nt][1] + q1) * v1;
            rsum[mt][1] += tanh_approx(acc[mt][nt][2] + q0) * v0
                         + tanh_approx(acc[mt][nt][3] + q1) * v1;
        }
    }
#pragma unroll
    for (int mt = 0; mt < 2; mt++) {
#pragma unroll
        for (int lh = 0; lh < 2; lh++) {
            float s = rsum[mt][lh];
            s += __shfl_xor_sync(0xffffffffu, s, 1);
            s += __shfl_xor_sync(0xffffffffu, s, 2);
            if ((lane & 3) == 0) {
                int r = wm * 32 + mt * 16 + (lane >> 2) + lh * 8;
                redf[r * 2 + wn] = s;
            }
        }
    }
    __syncthreads();
    if (tid < 128) {
        float s = redf[tid * 2] + redf[tid * 2 + 1];
        scorepart[(row0 + tid) * 2 + nh] = s;
    }
}

// ------------------------- softmax over T per batch -------------------------
__global__ void softmax_kernel(const float* __restrict__ sp,
                               float* __restrict__ attn) {
    int b = blockIdx.x;
    int tid = threadIdx.x;
    __shared__ float red[256];
    float v[8];
    float mx = -1e30f;
#pragma unroll
    for (int i = 0; i < 8; i++) {
        int t = i * 256 + tid;
        float s = sp[(b * TSEQ + t) * 2] + sp[(b * TSEQ + t) * 2 + 1];
        v[i] = s;
        mx = fmaxf(mx, s);
    }
    red[tid] = mx;
    __syncthreads();
    for (int o = 128; o > 0; o >>= 1) {
        if (tid < o) red[tid] = fmaxf(red[tid], red[tid + o]);
        __syncthreads();
    }
    mx = red[0];
    __syncthreads();
    float sum = 0.f;
#pragma unroll
    for (int i = 0; i < 8; i++) {
        v[i] = expf(v[i] - mx);
        sum += v[i];
    }
    red[tid] = sum;
    __syncthreads();
    for (int o = 128; o > 0; o >>= 1) {
        if (tid < o) red[tid] += red[tid + o];
        __syncthreads();
    }
    float inv = 1.f / red[0];
#pragma unroll
    for (int i = 0; i < 8; i++) attn[b * TSEQ + i * 256 + tid] = v[i] * inv;
}

// ------------------------- ctx_vec = sum_t attn * context -------------------
// grid (64, 16), 128 threads; 128 t per chunk
__global__ void ctx_partial_kernel(const float* __restrict__ context,
                                   const float* __restrict__ attn,
                                   float* __restrict__ partial) {
    int b = blockIdx.x, tc = blockIdx.y;
    int tid = threadIdx.x;
    __shared__ float sa[128];
    sa[tid] = attn[b * TSEQ + tc * 128 + tid];
    __syncthreads();
    const float4* ctx4 =
        (const float4*)context + ((size_t)b * TSEQ + tc * 128) * 128;
    float ax = 0.f, ay = 0.f, az = 0.f, aw = 0.f;
#pragma unroll 8
    for (int t = 0; t < 128; t++) {
        float a = sa[t];
        float4 v = ctx4[(size_t)t * 128 + tid];
        ax = fmaf(a, v.x, ax);
        ay = fmaf(a, v.y, ay);
        az = fmaf(a, v.z, az);
        aw = fmaf(a, v.w, aw);
    }
    float4 r = make_float4(ax, ay, az, aw);
    ((float4*)partial)[(size_t)(b * 16 + tc) * 128 + tid] = r;
}

__global__ void ctx_reduce_kernel(const float* __restrict__ partial,
                                  float* __restrict__ ctxvec) {
    int idx = blockIdx.x * 256 + threadIdx.x;   // 32768
    int b = idx >> 9, u = idx & 511;
    float s = 0.f;
#pragma unroll
    for (int tc = 0; tc < 16; tc++) s += partial[(size_t)(b * 16 + tc) * UNITS + u];
    ctxvec[idx] = s;
}

// ------------------------- gates -------------------------------------------
__global__ void gate_kernel(const float* __restrict__ xg,
                            const float* __restrict__ reczr,
                            const float* __restrict__ cg,
                            const float* __restrict__ h_tm1,
                            float* __restrict__ zbuf,
                            float* __restrict__ rh) {
    int idx = blockIdx.x * 256 + threadIdx.x;
    int b = idx >> 9, n = idx & 511;
    float zin = xg[b * 1536 + n] + reczr[b * 1024 + n] + cg[b * 1536 + n];
    float rin = xg[b * 1536 + 512 + n] + reczr[b * 1024 + 512 + n] +
                cg[b * 1536 + 512 + n];
    float z = 1.f / (1.f + expf(-zin));
    float r = 1.f / (1.f + expf(-rin));
    zbuf[idx] = z;
    rh[idx] = r * h_tm1[idx];
}

// ------------------------- h epilogue (reduce rec_h partials) ----------------
// grid (2, 64)
__global__ void hfinal_reduce_kernel(const float* __restrict__ P,
                                     const float* __restrict__ xg,
                                     const float* __restrict__ cg,
                                     const float* __restrict__ zbuf,
                                     const float* __restrict__ h_tm1,
                                     float* __restrict__ hbuf,
                                     float* __restrict__ outh) {
    int m = blockIdx.y;
    int n = blockIdx.x * 256 + threadIdx.x;
    float rec_h = 0.f;
#pragma unroll
    for (int ks = 0; ks < 4; ks++) rec_h += P[(size_t)(ks * 64 + m) * 512 + n];
    float hb = tanhf(xg[m * 1536 + 1024 + n] + rec_h + cg[m * 1536 + 1024 + n]);
    float z = zbuf[m * UNITS + n];
    float h = z * h_tm1[m * UNITS + n] + (1.f - z) * hb;
    hbuf[m * UNITS + n] = h;
    outh[m * UNITS + n] = h;
}

// ---------------------------------------------------------------------------
extern "C" void kernel_launch(void* const* d_in, const int* in_sizes, int n_in,
                              void* d_out, int out_size) {
    const float* inputs  = (const float*)d_in[0];
    const float* h_tm1   = (const float*)d_in[1];
    const float* context = (const float*)d_in[2];
    const float* Wi      = (const float*)d_in[3];
    const float* bi      = (const float*)d_in[4];
    const float* kern    = (const float*)d_in[5];
    const float* reck    = (const float*)d_in[6];
    const float* attk    = (const float*)d_in[7];
    const float* bias    = (const float*)d_in[8];
    const float* Wa      = (const float*)d_in[9];
    const float* ba_w    = (const float*)d_in[10];
    const float* Ua      = (const float*)d_in[11];
    const float* ba_u    = (const float*)d_in[12];
    const float* Va      = (const float*)d_in[13];
    /* ba_v (d_in[14]) cancels in softmax */
    const float* Wo      = (const float*)d_in[15];
    const float* bo      = (const float*)d_in[16];

    float* out  = (float*)d_out;
    float* outh = out + BATCH * UNITS;

    float *px, *pxg, *pq, *prec, *psp, *pat, *ppar, *pcv, *pcg, *pz, *prh, *ph, *pgp;
    __nv_bfloat16* pwat;
    void* tmp;
    cudaGetSymbolAddress(&tmp, g_x);         px   = (float*)tmp;
    cudaGetSymbolAddress(&tmp, g_xg);        pxg  = (float*)tmp;
    cudaGetSymbolAddress(&tmp, g_qplus);     pq   = (float*)tmp;
    cudaGetSymbolAddress(&tmp, g_reczr);     prec = (float*)tmp;
    cudaGetSymbolAddress(&tmp, g_scorepart); psp  = (float*)tmp;
    cudaGetSymbolAddress(&tmp, g_attn);      pat  = (float*)tmp;
    cudaGetSymbolAddress(&tmp, g_partial);   ppar = (float*)tmp;
    cudaGetSymbolAddress(&tmp, g_ctxvec);    pcv  = (float*)tmp;
    cudaGetSymbolAddress(&tmp, g_cg);        pcg  = (float*)tmp;
    cudaGetSymbolAddress(&tmp, g_z);         pz   = (float*)tmp;
    cudaGetSymbolAddress(&tmp, g_rh);        prh  = (float*)tmp;
    cudaGetSymbolAddress(&tmp, g_h);         ph   = (float*)tmp;
    cudaGetSymbolAddress(&tmp, g_gp);        pgp  = (float*)tmp;
    cudaGetSymbolAddress(&tmp, g_WaT);       pwat = (__nv_bfloat16*)tmp;

    // 1. Wa -> bf16 transposed (coalesced)
    prep_wat_kernel<<<dim3(16, 16), dim3(32, 8)>>>(Wa, pwat);

    // 2. x = inputs @ Wi + bi   (K=256, KS=2)
    gemm64_kernel<<<dim3(8, 2), 256>>>(inputs, EMB, Wi, 512, 0, 128, pgp, 512);
    reduce64_kernel<<<dim3(2, 64), 256>>>(pgp, 512, 2, bi, nullptr, px, 512, 0);
    // 3. xg = x @ kernel + bias   (N=1536, KS=4)
    gemm64_kernel<<<dim3(24, 4), 256>>>(px, 512, kern, 1536, 0, 128, pgp, 1536);
    reduce64_kernel<<<dim3(6, 64), 256>>>(pgp, 1536, 4, bias, nullptr, pxg, 1536, 0);
    // 4. qplus = h_tm1 @ Ua + ba_u + ba_w
    gemm64_kernel<<<dim3(8, 4), 256>>>(h_tm1, 512, Ua, 512, 0, 128, pgp, 512);
    reduce64_kernel<<<dim3(2, 64), 256>>>(pgp, 512, 4, ba_u, ba_w, pq, 512, 0);
    // 5. rec_{z,r} = h_tm1 @ reck[:, :1024]
    gemm64_kernel<<<dim3(16, 4), 256>>>(h_tm1, 512, reck, 1536, 0, 128, pgp, 1024);
    reduce64_kernel<<<dim3(4, 64), 256>>>(pgp, 1024, 4, nullptr, nullptr, prec, 1024, 0);

    // 6. big fused score GEMM (bf16 mma, cp.async double buffered)
    const int smem_bytes = (2 * SBM * SASTR + 2 * SBN * SBSTR) * 4;   // 147456
    cudaFuncSetAttribute((const void*)score_kernel,
                         cudaFuncAttributeMaxDynamicSharedMemorySize, smem_bytes);
    score_kernel<<<dim3(ROWS / SBM, 2), 256, smem_bytes>>>(context, pwat, pq, Va, psp);

    // 7. softmax over T
    softmax_kernel<<<BATCH, 256>>>(psp, pat);
    // 8-9. ctx_vec = sum_t attn * context
    ctx_partial_kernel<<<dim3(BATCH, 16), 128>>>(context, pat, ppar);
    ctx_reduce_kernel<<<BATCH * UNITS / 256, 256>>>(ppar, pcv);
    // 10. cg = ctx_vec @ attention_kernel
    gemm64_kernel<<<dim3(24, 4), 256>>>(pcv, 512, attk, 1536, 0, 128, pgp, 1536);
    reduce64_kernel<<<dim3(6, 64), 256>>>(pgp, 1536, 4, nullptr, nullptr, pcg, 1536, 0);
    // 11. z, r gates
    gate_kernel<<<BATCH * UNITS / 256, 256>>>(pxg, prec, pcg, h_tm1, pz, prh);
    // 12. rec_h = rh @ reck[:, 1024:]  + h epilogue
    gemm64_kernel<<<dim3(8, 4), 256>>>(prh, 512, reck, 1536, 1024, 128, pgp, 512);
    hfinal_reduce_kernel<<<dim3(2, 64), 256>>>(pgp, pxg, pcg, pz, h_tm1, ph, outh);
    // 13. out = h @ Wo + bo
    gemm64_kernel<<<dim3(8, 4), 256>>>(ph, 512, Wo, 512, 0, 128, pgp, 512);
    reduce64_kernel<<<dim3(2, 64), 256>>>(pgp, 512, 4, bo, nullptr, out, 512, 0);

    (void)in_sizes; (void)n_in; (void)out_size;
}

// round 9
// speedup vs baseline: 1.1491x; 1.1491x over previous
#include <cuda_runtime.h>
#include <cuda_bf16.h>
#include <math.h>
#include <stdint.h>

#define BATCH 64
#define TSEQ  2048
#define UNITS 512
#define EMB   256
#define ROWS  (BATCH * TSEQ)   // 131072

// ------------------------- device scratch ----------------------------------
__device__ float g_x[BATCH * UNITS];
__device__ float g_xg[BATCH * 3 * UNITS];
__device__ float g_qplus[BATCH * UNITS];
__device__ float g_reczr[BATCH * 2 * UNITS];
__device__ float g_scorepart[ROWS * 2];
__device__ float g_attn[BATCH * TSEQ];
__device__ float g_partial[BATCH * 16 * UNITS];
__device__ float g_ctxvec[BATCH * UNITS];
__device__ float g_cg[BATCH * 3 * UNITS];
__device__ float g_z[BATCH * UNITS];
__device__ float g_rh[BATCH * UNITS];
__device__ float g_h[BATCH * UNITS];
__device__ float g_gp[1048576];                      // split-K partials (4MB)
__device__ __nv_bfloat16 g_WaT[UNITS * UNITS];       // [n][k], k contiguous

// partial regions inside g_gp for the merged pre-score GEMMs
#define GP_X  0          // [4][64][512]
#define GP_Q  131072     // [8][64][512]
#define GP_R  393216     // [8][64][1024]

// ------------------------- helpers -----------------------------------------
__device__ __forceinline__ void cp16(void* dst_smem, const void* src) {
    uint32_t d = (uint32_t)__cvta_generic_to_shared(dst_smem);
    asm volatile("cp.async.cg.shared.global [%0], [%1], 16;\n" :: "r"(d), "l"(src));
}
#define CP_COMMIT() asm volatile("cp.async.commit_group;\n" ::)
#define CP_WAIT1()  asm volatile("cp.async.wait_group 1;\n" ::)
#define CP_WAIT0()  asm volatile("cp.async.wait_group 0;\n" ::)

__device__ __forceinline__ float tanh_approx(float x) {
    float y;
    asm("tanh.approx.f32 %0, %1;" : "=f"(y) : "f"(x));
    return y;
}
__device__ __forceinline__ uint32_t packbf(float a, float b) {
    __nv_bfloat162 p = __floats2bfloat162_rn(a, b);
    return *(uint32_t*)&p;
}

// ------------------------- prep: Wa -> WaT bf16 (tiled transpose) -----------
__global__ void prep_wat_kernel(const float* __restrict__ Wa,
                                __nv_bfloat16* __restrict__ WaT) {
    __shared__ float t[32][33];
    int n0 = blockIdx.x * 32, k0 = blockIdx.y * 32;
    int tx = threadIdx.x, ty = threadIdx.y;     // 32 x 8
#pragma unroll
    for (int i = 0; i < 4; i++)
        t[ty + 8 * i][tx] = Wa[(k0 + ty + 8 * i) * UNITS + n0 + tx];
    __syncthreads();
#pragma unroll
    for (int i = 0; i < 4; i++)
        WaT[(size_t)(n0 + ty + 8 * i) * UNITS + k0 + tx] =
            __float2bfloat16(t[tx][ty + 8 * i]);
}

// ------------------------- shared 64x64 GEMM body ---------------------------
__device__ __forceinline__ void gemm64_body(
    float (*As_t)[68], float (*Bs)[68],
    const float* __restrict__ A, int lda,
    const float* __restrict__ B, int ldb, int bcol0,
    int k0, int Kc, float* __restrict__ P, int N, int outn, int prow0) {
    int tid = threadIdx.x;
    int tx = tid & 15, ty = tid >> 4;
    float acc[4][4];
#pragma unroll
    for (int i = 0; i < 4; i++)
#pragma unroll
        for (int j = 0; j < 4; j++) acc[i][j] = 0.f;

    int am = tid >> 2, aj = tid & 3;
    int bk = tid >> 4, bf = tid & 15;

    for (int kb = 0; kb < Kc; kb += 16) {
        float4 av = *(const float4*)&A[am * lda + k0 + kb + aj * 4];
        float4 bv = *(const float4*)&B[(size_t)(k0 + kb + bk) * ldb + bcol0 + bf * 4];
        As_t[aj * 4 + 0][am] = av.x;
        As_t[aj * 4 + 1][am] = av.y;
        As_t[aj * 4 + 2][am] = av.z;
        As_t[aj * 4 + 3][am] = av.w;
        *(float4*)&Bs[bk][bf * 4] = bv;
        __syncthreads();
#pragma unroll
        for (int k = 0; k < 16; k++) {
            float4 a = *(const float4*)&As_t[k][ty * 4];
            float4 b = *(const float4*)&Bs[k][tx * 4];
            acc[0][0] = fmaf(a.x, b.x, acc[0][0]);
            acc[0][1] = fmaf(a.x, b.y, acc[0][1]);
            acc[0][2] = fmaf(a.x, b.z, acc[0][2]);
            acc[0][3] = fmaf(a.x, b.w, acc[0][3]);
            acc[1][0] = fmaf(a.y, b.x, acc[1][0]);
            acc[1][1] = fmaf(a.y, b.y, acc[1][1]);
            acc[1][2] = fmaf(a.y, b.z, acc[1][2]);
            acc[1][3] = fmaf(a.y, b.w, acc[1][3]);
            acc[2][0] = fmaf(a.z, b.x, acc[2][0]);
            acc[2][1] = fmaf(a.z, b.y, acc[2][1]);
            acc[2][2] = fmaf(a.z, b.z, acc[2][2]);
            acc[2][3] = fmaf(a.z, b.w, acc[2][3]);
            acc[3][0] = fmaf(a.w, b.x, acc[3][0]);
            acc[3][1] = fmaf(a.w, b.y, acc[3][1]);
            acc[3][2] = fmaf(a.w, b.z, acc[3][2]);
            acc[3][3] = fmaf(a.w, b.w, acc[3][3]);
        }
        __syncthreads();
    }
#pragma unroll
    for (int i = 0; i < 4; i++) {
        float4 r = make_float4(acc[i][0], acc[i][1], acc[i][2], acc[i][3]);
        *(float4*)&P[(size_t)(prow0 + ty * 4 + i) * N + outn + tx * 4] = r;
    }
}

// generic wrapper: grid (nblk, KS), Kc = 64
__global__ __launch_bounds__(256)
void gemm64_kernel(const float* __restrict__ A, int lda,
                   const float* __restrict__ B, int ldb, int bcol0,
                   float* __restrict__ P, int N) {
    __shared__ float As_t[16][68];
    __shared__ float Bs[16][68];
    int n0 = blockIdx.x * 64;
    int ks = blockIdx.y;
    gemm64_body(As_t, Bs, A, lda, B, ldb, bcol0 + n0, ks * 64, 64, P, N, n0, ks * 64);
}

// merged pre-score GEMMs: x (32 CTAs), qplus (64), reczr (128) -> 224 CTAs
__global__ __launch_bounds__(256)
void gemm64_multi_kernel(const float* __restrict__ inputs,
                         const float* __restrict__ h_tm1,
                         const float* __restrict__ Wi,
                         const float* __restrict__ Ua,
                         const float* __restrict__ reck,
                         float* __restrict__ gp) {
    __shared__ float As_t[16][68];
    __shared__ float Bs[16][68];
    int bid = blockIdx.x;
    if (bid < 32) {            // x = inputs @ Wi   (K=256, KS=4)
        int nb = bid & 7, ks = bid >> 3;
        gemm64_body(As_t, Bs, inputs, EMB, Wi, 512, nb * 64, ks * 64, 64,
                    gp + GP_X, 512, nb * 64, ks * 64);
    } else if (bid < 96) {     // qplus = h_tm1 @ Ua (K=512, KS=8)
        int idx = bid - 32;
        int nb = idx & 7, ks = idx >> 3;
        gemm64_body(As_t, Bs, h_tm1, 512, Ua, 512, nb * 64, ks * 64, 64,
                    gp + GP_Q, 512, nb * 64, ks * 64);
    } else {                   // reczr = h_tm1 @ reck[:, :1024] (KS=8)
        int idx = bid - 96;
        int nb = idx & 15, ks = idx >> 4;
        gemm64_body(As_t, Bs, h_tm1, 512, reck, 1536, nb * 64, ks * 64, 64,
                    gp + GP_R, 1024, nb * 64, ks * 64);
    }
}

// merged reduce for x / qplus / reczr. grid 512 x 256
__global__ void reduce_multi_kernel(const float* __restrict__ gp,
                                    const float* __restrict__ bi,
                                    const float* __restrict__ ba_u,
                                    const float* __restrict__ ba_w,
                                    float* __restrict__ x,
                                    float* __restrict__ qplus,
                                    float* __restrict__ reczr) {
    int idx = blockIdx.x * 256 + threadIdx.x;   // 0..131071
    if (idx < 32768) {
        int m = idx >> 9, n = idx & 511;
        float s = 0.f;
#pragma unroll
        for (int ks = 0; ks < 4; ks++) s += gp[GP_X + (size_t)(ks * 64 + m) * 512 + n];
        x[m * 512 + n] = s + bi[n];
    } else if (idx < 65536) {
        int i = idx - 32768;
        int m = i >> 9, n = i & 511;
        float s = 0.f;
#pragma unroll
        for (int ks = 0; ks < 8; ks++) s += gp[GP_Q + (size_t)(ks * 64 + m) * 512 + n];
        qplus[m * 512 + n] = s + ba_u[n] + ba_w[n];
    } else {
        int i = idx - 65536;
        int m = i >> 10, n = i & 1023;
        float s = 0.f;
#pragma unroll
        for (int ks = 0; ks < 8; ks++) s += gp[GP_R + (size_t)(ks * 64 + m) * 1024 + n];
        reczr[m * 1024 + n] = s;
    }
}

// reduce over split-K + biases. grid (N/256, 64)
__global__ void reduce64_kernel(const float* __restrict__ P, int N, int KS,
                                const float* __restrict__ b1,
                                float* __restrict__ C, int ldc) {
    int m = blockIdx.y;
    int n = blockIdx.x * 256 + threadIdx.x;
    float s = 0.f;
    for (int ks = 0; ks < KS; ks++) s += P[(size_t)(ks * 64 + m) * N + n];
    if (b1) s += b1[n];
    C[m * ldc + n] = s;
}

// ------------------------- big fused score GEMM (cp.async + ldmatrix B) -----
#define SBM 128
#define SBN 256
#define SASTR 72   // fp32 per A smem row (64 + 8 pad)
#define SBSTR 36   // u32 per B smem row (32 + 4 pad)

__device__ __forceinline__ void score_issue(
    int tid, const float* gA, const __nv_bfloat16* gB,
    float* As, uint32_t* Bs) {
#pragma unroll
    for (int i = 0; i < 8; i++) {
        int c = tid + i * 256;
        int r = c >> 4, f = c & 15;
        cp16(As + r * SASTR + f * 4, gA + (size_t)r * UNITS + f * 4);
    }
#pragma unroll
    for (int i = 0; i < 8; i++) {
        int c = tid + i * 256;
        int n = c >> 3, j = c & 7;
        cp16(Bs + n * SBSTR + j * 4, gB + (size_t)n * UNITS + j * 8);
    }
}

__global__ __launch_bounds__(256, 1)
void score_kernel(const float* __restrict__ context,
                  const __nv_bfloat16* __restrict__ WaT,
                  const float* __restrict__ qplus,
                  const float* __restrict__ Va,
                  float* __restrict__ scorepart) {
    extern __shared__ uint32_t smem[];
    float* Ast[2];
    uint32_t* Bst[2];
    Ast[0] = (float*)smem;
    Ast[1] = Ast[0] + SBM * SASTR;
    Bst[0] = (uint32_t*)(Ast[1] + SBM * SASTR);
    Bst[1] = Bst[0] + SBN * SBSTR;

    const int tid = threadIdx.x;
    const int wid = tid >> 5;
    const int lane = tid & 31;
    const int wm = wid >> 1;
    const int wn = wid & 1;
    const size_t row0 = (size_t)blockIdx.x * SBM;
    const int b = (int)(row0 >> 11);
    const int nh = blockIdx.y;
    const int ncol0 = nh * SBN;

    const float* gA = context + row0 * UNITS;
    const __nv_bfloat16* gB = WaT + (size_t)ncol0 * UNITS;

    float acc[2][16][4];
#pragma unroll
    for (int i = 0; i < 2; i++)
#pragma unroll
        for (int j = 0; j < 16; j++)
#pragma unroll
            for (int q = 0; q < 4; q++) acc[i][j][q] = 0.f;

    // ldmatrix lane mapping (constant per thread)
    const int b_rowoff = (lane & 7) + ((lane & 16) ? 8 : 0);
    const int b_coff = (lane >> 3) & 1;

    score_issue(tid, gA, gB, Ast[0], Bst[0]);
    CP_COMMIT();

    for (int kt = 0; kt < 8; ++kt) {
        if (kt < 7) {
            score_issue(tid, gA + (kt + 1) * 64, gB + (kt + 1) * 64,
                        Ast[(kt + 1) & 1], Bst[(kt + 1) & 1]);
            CP_COMMIT();
            CP_WAIT1();
        } else {
            CP_WAIT0();
        }
        __syncthreads();

        const float* As = Ast[kt & 1];
        uint32_t* Bs = Bst[kt & 1];
        const uint32_t bsh = (uint32_t)__cvta_generic_to_shared(Bs);
#pragma unroll
        for (int ks = 0; ks < 4; ks++) {
            uint32_t a[2][4];
            int kk = ks * 16 + (lane & 3) * 2;
#pragma unroll
            for (int mt = 0; mt < 2; mt++) {
                int r0 = wm * 32 + mt * 16 + (lane >> 2);
                float2 f0 = *(const float2*)&As[r0 * SASTR + kk];
                float2 f1 = *(const float2*)&As[(r0 + 8) * SASTR + kk];
                float2 f2 = *(const float2*)&As[r0 * SASTR + kk + 8];
                float2 f3 = *(const float2*)&As[(r0 + 8) * SASTR + kk + 8];
                a[mt][0] = packbf(f0.x, f0.y);
                a[mt][1] = packbf(f1.x, f1.y);
                a[mt][2] = packbf(f2.x, f2.y);
                a[mt][3] = packbf(f3.x, f3.y);
            }
#pragma unroll
            for (int np = 0; np < 8; np++) {
                int nrow = wn * 128 + np * 16 + b_rowoff;
                uint32_t addr = bsh + (uint32_t)(nrow * SBSTR + (ks * 2 + b_coff) * 4) * 4u;
                uint32_t b0, b1, b2, b3;
                asm volatile(
                    "ldmatrix.sync.aligned.m8n8.x4.shared.b16 {%0,%1,%2,%3}, [%4];"
                    : "=r"(b0), "=r"(b1), "=r"(b2), "=r"(b3) : "r"(addr));
#pragma unroll
                for (int mt = 0; mt < 2; mt++) {
                    asm volatile(
                        "mma.sync.aligned.m16n8k16.row.col.f32.bf16.bf16.f32 "
                        "{%0,%1,%2,%3}, {%4,%5,%6,%7}, {%8,%9}, {%0,%1,%2,%3};\n"
                        : "+f"(acc[mt][np * 2][0]), "+f"(acc[mt][np * 2][1]),
                          "+f"(acc[mt][np * 2][2]), "+f"(acc[mt][np * 2][3])
                        : "r"(a[mt][0]), "r"(a[mt][1]), "r"(a[mt][2]), "r"(a[mt][3]),
                          "r"(b0), "r"(b1));
                    asm volatile(
                        "mma.sync.aligned.m16n8k16.row.col.f32.bf16.bf16.f32 "
                        "{%0,%1,%2,%3}, {%4,%5,%6,%7}, {%8,%9}, {%0,%1,%2,%3};\n"
                        : "+f"(acc[mt][np * 2 + 1][0]), "+f"(acc[mt][np * 2 + 1][1]),
                          "+f"(acc[mt][np * 2 + 1][2]), "+f"(acc[mt][np * 2 + 1][3])
                        : "r"(a[mt][0]), "r"(a[mt][1]), "r"(a[mt][2]), "r"(a[mt][3]),
                          "r"(b2), "r"(b3));
                }
            }
        }
        __syncthreads();
    }

    // ---- epilogue: +qplus -> tanh -> *Va -> row reduce ----
    float* redf = (float*)smem;          // [128][2]
    float* sq = redf + 256;              // [512]
    float* sv = sq + 512;                // [512]
    for (int i = tid; i < 512; i += 256) {
        sq[i] = qplus[b * UNITS + i];
        sv[i] = Va[i];
    }
    __syncthreads();

    float rsum[2][2] = {{0.f, 0.f}, {0.f, 0.f}};
#pragma unroll
    for (int mt = 0; mt < 2; mt++) {
#pragma unroll
        for (int nt = 0; nt < 16; nt++) {
            int n0 = ncol0 + wn * 128 + nt * 8 + (lane & 3) * 2;
            float q0 = sq[n0], q1 = sq[n0 + 1];
            float v0 = sv[n0], v1 = sv[n0 + 1];
            rsum[mt][0] += tanh_approx(acc[mt][nt][0] + q0) * v0
                         + tanh_approx(acc[mt][nt][1] + q1) * v1;
            rsum[mt][1] += tanh_approx(acc[mt][nt][2] + q0) * v0
                         + tanh_approx(acc[mt][nt][3] + q1) * v1;
        }
    }
#pragma unroll
    for (int mt = 0; mt < 2; mt++) {
#pragma unroll
        for (int lh = 0; lh < 2; lh++) {
            float s = rsum[mt][lh];
            s += __shfl_xor_sync(0xffffffffu, s, 1);
            s += __shfl_xor_sync(0xffffffffu, s, 2);
            if ((lane & 3) == 0) {
                int r = wm * 32 + mt * 16 + (lane >> 2) + lh * 8;
                redf[r * 2 + wn] = s;
            }
        }
    }
    __syncthreads();
    if (tid < 128) {
        float s = redf[tid * 2] + redf[tid * 2 + 1];
        scorepart[(row0 + tid) * 2 + nh] = s;
    }
}

// ------------------------- softmax over T per batch -------------------------
__global__ void softmax_kernel(const float* __restrict__ sp,
                               float* __restrict__ attn) {
    int b = blockIdx.x;
    int tid = threadIdx.x;
    __shared__ float red[256];
    float v[8];
    float mx = -1e30f;
#pragma unroll
    for (int i = 0; i < 8; i++) {
        int t = i * 256 + tid;
        float s = sp[(b * TSEQ + t) * 2] + sp[(b * TSEQ + t) * 2 + 1];
        v[i] = s;
        mx = fmaxf(mx, s);
    }
    red[tid] = mx;
    __syncthreads();
    for (int o = 128; o > 0; o >>= 1) {
        if (tid < o) red[tid] = fmaxf(red[tid], red[tid + o]);
        __syncthreads();
    }
    mx = red[0];
    __syncthreads();
    float sum = 0.f;
#pragma unroll
    for (int i = 0; i < 8; i++) {
        v[i] = expf(v[i] - mx);
        sum += v[i];
    }
    red[tid] = sum;
    __syncthreads();
    for (int o = 128; o > 0; o >>= 1) {
        if (tid < o) red[tid] += red[tid + o];
        __syncthreads();
    }
    float inv = 1.f / red[0];
#pragma unroll
    for (int i = 0; i < 8; i++) attn[b * TSEQ + i * 256 + tid] = v[i] * inv;
}

// ------------------------- ctx_vec = sum_t attn * context -------------------
__global__ void ctx_partial_kernel(const float* __restrict__ context,
                                   const float* __restrict__ attn,
                                   float* __restrict__ partial) {
    int b = blockIdx.x, tc = blockIdx.y;
    int tid = threadIdx.x;
    __shared__ float sa[128];
    sa[tid] = attn[b * TSEQ + tc * 128 + tid];
    __syncthreads();
    const float4* ctx4 =
        (const float4*)context + ((size_t)b * TSEQ + tc * 128) * 128;
    float ax = 0.f, ay = 0.f, az = 0.f, aw = 0.f;
#pragma unroll 8
    for (int t = 0; t < 128; t++) {
        float a = sa[t];
        float4 v = ctx4[(size_t)t * 128 + tid];
        ax = fmaf(a, v.x, ax);
        ay = fmaf(a, v.y, ay);
        az = fmaf(a, v.z, az);
        aw = fmaf(a, v.w, aw);
    }
    float4 r = make_float4(ax, ay, az, aw);
    ((float4*)partial)[(size_t)(b * 16 + tc) * 128 + tid] = r;
}

__global__ void ctx_reduce_kernel(const float* __restrict__ partial,
                                  float* __restrict__ ctxvec) {
    int idx = blockIdx.x * 256 + threadIdx.x;   // 32768
    int b = idx >> 9, u = idx & 511;
    float s = 0.f;
#pragma unroll
    for (int tc = 0; tc < 16; tc++) s += partial[(size_t)(b * 16 + tc) * UNITS + u];
    ctxvec[idx] = s;
}

// ------------------------- gates -------------------------------------------
__global__ void gate_kernel(const float* __restrict__ xg,
                            const float* __restrict__ reczr,
                            const float* __restrict__ cg,
                            const float* __restrict__ h_tm1,
                            float* __restrict__ zbuf,
                            float* __restrict__ rh) {
    int idx = blockIdx.x * 256 + threadIdx.x;
    int b = idx >> 9, n = idx & 511;
    float zin = xg[b * 1536 + n] + reczr[b * 1024 + n] + cg[b * 1536 + n];
    float rin = xg[b * 1536 + 512 + n] + reczr[b * 1024 + 512 + n] +
                cg[b * 1536 + 512 + n];
    float z = 1.f / (1.f + expf(-zin));
    float r = 1.f / (1.f + expf(-rin));
    zbuf[idx] = z;
    rh[idx] = r * h_tm1[idx];
}

// ------------------------- h epilogue (reduce rec_h partials) ----------------
__global__ void hfinal_reduce_kernel(const float* __restrict__ P,
                                     const float* __restrict__ xg,
                                     const float* __restrict__ cg,
                                     const float* __restrict__ zbuf,
                                     const float* __restrict__ h_tm1,
                                     float* __restrict__ hbuf,
                                     float* __restrict__ outh) {
    int m = blockIdx.y;
    int n = blockIdx.x * 256 + threadIdx.x;
    float rec_h = 0.f;
#pragma unroll
    for (int ks = 0; ks < 8; ks++) rec_h += P[(size_t)(ks * 64 + m) * 512 + n];
    float hb = tanhf(xg[m * 1536 + 1024 + n] + rec_h + cg[m * 1536 + 1024 + n]);
    float z = zbuf[m * UNITS + n];
    float h = z * h_tm1[m * UNITS + n] + (1.f - z) * hb;
    hbuf[m * UNITS + n] = h;
    outh[m * UNITS + n] = h;
}

// ---------------------------------------------------------------------------
extern "C" void kernel_launch(void* const* d_in, const int* in_sizes, int n_in,
                              void* d_out, int out_size) {
    const float* inputs  = (const float*)d_in[0];
    const float* h_tm1   = (const float*)d_in[1];
    const float* context = (const float*)d_in[2];
    const float* Wi      = (const float*)d_in[3];
    const float* bi      = (const float*)d_in[4];
    const float* kern    = (const float*)d_in[5];
    const float* reck    = (const float*)d_in[6];
    const float* attk    = (const float*)d_in[7];
    const float* bias    = (const float*)d_in[8];
    const float* Wa      = (const float*)d_in[9];
    const float* ba_w    = (const float*)d_in[10];
    const float* Ua      = (const float*)d_in[11];
    const float* ba_u    = (const float*)d_in[12];
    const float* Va      = (const float*)d_in[13];
    /* ba_v (d_in[14]) cancels in softmax */
    const float* Wo      = (const float*)d_in[15];
    const float* bo      = (const float*)d_in[16];

    float* out  = (float*)d_out;
    float* outh = out + BATCH * UNITS;

    float *px, *pxg, *pq, *prec, *psp, *pat, *ppar, *pcv, *pcg, *pz, *prh, *ph, *pgp;
    __nv_bfloat16* pwat;
    void* tmp;
    cudaGetSymbolAddress(&tmp, g_x);         px   = (float*)tmp;
    cudaGetSymbolAddress(&tmp, g_xg);        pxg  = (float*)tmp;
    cudaGetSymbolAddress(&tmp, g_qplus);     pq   = (float*)tmp;
    cudaGetSymbolAddress(&tmp, g_reczr);     prec = (float*)tmp;
    cudaGetSymbolAddress(&tmp, g_scorepart); psp  = (float*)tmp;
    cudaGetSymbolAddress(&tmp, g_attn);      pat  = (float*)tmp;
    cudaGetSymbolAddress(&tmp, g_partial);   ppar = (float*)tmp;
    cudaGetSymbolAddress(&tmp, g_ctxvec);    pcv  = (float*)tmp;
    cudaGetSymbolAddress(&tmp, g_cg);        pcg  = (float*)tmp;
    cudaGetSymbolAddress(&tmp, g_z);         pz   = (float*)tmp;
    cudaGetSymbolAddress(&tmp, g_rh);        prh  = (float*)tmp;
    cudaGetSymbolAddress(&tmp, g_h);         ph   = (float*)tmp;
    cudaGetSymbolAddress(&tmp, g_gp);        pgp  = (float*)tmp;
    cudaGetSymbolAddress(&tmp, g_WaT);       pwat = (__nv_bfloat16*)tmp;

    // 1. Wa -> bf16 transposed
    prep_wat_kernel<<<dim3(16, 16), dim3(32, 8)>>>(Wa, pwat);

    // 2. merged: x = inputs@Wi ; qplus = h_tm1@Ua ; reczr = h_tm1@reck[:,:1024]
    gemm64_multi_kernel<<<224, 256>>>(inputs, h_tm1, Wi, Ua, reck, pgp);
    reduce_multi_kernel<<<512, 256>>>(pgp, bi, ba_u, ba_w, px, pq, prec);

    // 3. xg = x @ kernel + bias   (KS=8)
    gemm64_kernel<<<dim3(24, 8), 256>>>(px, 512, kern, 1536, 0, pgp, 1536);
    reduce64_kernel<<<dim3(6, 64), 256>>>(pgp, 1536, 8, bias, pxg, 1536);

    // 4. big fused score GEMM (bf16 mma + ldmatrix B, cp.async 2-stage)
    const int smem_bytes = (2 * SBM * SASTR + 2 * SBN * SBSTR) * 4;   // 147456
    cudaFuncSetAttribute((const void*)score_kernel,
                         cudaFuncAttributeMaxDynamicSharedMemorySize, smem_bytes);
    score_kernel<<<dim3(ROWS / SBM, 2), 256, smem_bytes>>>(context, pwat, pq, Va, psp);

    // 5. softmax over T
    softmax_kernel<<<BATCH, 256>>>(psp, pat);
    // 6. ctx_vec = sum_t attn * context
    ctx_partial_kernel<<<dim3(BATCH, 16), 128>>>(context, pat, ppar);
    ctx_reduce_kernel<<<BATCH * UNITS / 256, 256>>>(ppar, pcv);
    // 7. cg = ctx_vec @ attention_kernel (KS=8)
    gemm64_kernel<<<dim3(24, 8), 256>>>(pcv, 512, attk, 1536, 0, pgp, 1536);
    reduce64_kernel<<<dim3(6, 64), 256>>>(pgp, 1536, 8, nullptr, pcg, 1536);
    // 8. z, r gates
    gate_kernel<<<BATCH * UNITS / 256, 256>>>(pxg, prec, pcg, h_tm1, pz, prh);
    // 9. rec_h = rh @ reck[:, 1024:] + h epilogue (KS=8)
    gemm64_kernel<<<dim3(8, 8), 256>>>(prh, 512, reck, 1536, 1024, pgp, 512);
    hfinal_reduce_kernel<<<dim3(2, 64), 256>>>(pgp, pxg, pcg, pz, h_tm1, ph, outh);
    // 10. out = h @ Wo + bo (KS=8)
    gemm64_kernel<<<dim3(8, 8), 256>>>(ph, 512, Wo, 512, 0, pgp, 512);
    reduce64_kernel<<<dim3(2, 64), 256>>>(pgp, 512, 8, bo, out, 512);

    (void)in_sizes; (void)n_in; (void)out_size;
}